// round 12
// baseline (speedup 1.0000x reference)
#include <cuda_runtime.h>
#include <cuda_bf16.h>

// Lightcone-truncated quantum circuit simulation.
//
// Reference: 25-qubit state vector, 8 layers of (RY on every qubit, then
// CNOT chain w=0..23), output = sum_{MSB=0}|amp|^2 - sum_{MSB=1}|amp|^2
// = <Z_{qubit 0}> (qubit w maps to bit 24-w of the flat index; qubit 0 = MSB).
//
// Heisenberg-picture lightcone: conjugating Z_0 backward, support grows by at
// most one qubit per layer (X on a CNOT control spreads one step up; the
// C23..C0 conjugation order prevents cascading within a layer). After 8
// layers support is within qubits {0..7}. All gates outside the support
// conjugate trivially, so <Z_0> of the full circuit equals <Z_0> of the
// circuit truncated to the first NQS qubits (RYs on q0..NQS-1, CNOTs
// w=0..NQS-2). We use NQS=12 for a 4-qubit safety margin; the 4096-amplitude
// simulation runs entirely in one block's shared memory.

#define NQ     25
#define DEPTH  8
#define NQS    12
#define SIZE   (1 << NQS)
#define THREADS 256

__global__ void __launch_bounds__(THREADS, 1)
lightcone_qsim_kernel(const float* __restrict__ theta, float* __restrict__ out)
{
    __shared__ double st[SIZE];
    __shared__ double red[THREADS / 32];

    const int tid = threadIdx.x;

    // |0...0>
    for (int i = tid; i < SIZE; i += THREADS) st[i] = 0.0;
    __syncthreads();
    if (tid == 0) st[0] = 1.0;
    __syncthreads();

    for (int layer = 0; layer < DEPTH; ++layer) {
        // --- RY on qubits 0..NQS-1 (qubit w <-> bit NQS-1-w) ---
        for (int w = 0; w < NQS; ++w) {
            const int b    = NQS - 1 - w;
            const int mask = 1 << b;
            const double ang = 0.5 * (double)theta[layer * NQ + w];
            const double c = cos(ang);
            const double s = sin(ang);
            const int half = SIZE >> 1;
            for (int idx = tid; idx < half; idx += THREADS) {
                const int low = idx & (mask - 1);
                const int hi  = (idx >> b) << (b + 1);
                const int i0  = hi | low;
                const int i1  = i0 | mask;
                const double a0 = st[i0];
                const double a1 = st[i1];
                st[i0] = c * a0 - s * a1;
                st[i1] = s * a0 + c * a1;
            }
            __syncthreads();
        }
        // --- CNOT chain w=0..NQS-2 (control bit bc = NQS-1-w, target bt = bc-1) ---
        for (int w = 0; w < NQS - 1; ++w) {
            const int bt    = NQS - 2 - w;         // target bit
            const int cmask = 1 << (bt + 1);       // control bit mask
            const int tmask = 1 << bt;             // target bit mask
            const int quarter = SIZE >> 2;
            for (int idx = tid; idx < quarter; idx += THREADS) {
                const int low = idx & (tmask - 1);
                const int hi  = (idx >> bt) << (bt + 2);
                const int i0  = hi | cmask | low;  // control=1, target=0
                const int i1  = i0 | tmask;        // control=1, target=1
                const double a = st[i0];
                st[i0] = st[i1];
                st[i1] = a;
            }
            __syncthreads();
        }
    }

    // --- <Z_0> = sum_i (-1)^{MSB(i)} amp_i^2 ---
    double part = 0.0;
    for (int i = tid; i < SIZE; i += THREADS) {
        const double a = st[i];
        part += (i & (SIZE >> 1)) ? (-a * a) : (a * a);
    }
    #pragma unroll
    for (int off = 16; off > 0; off >>= 1)
        part += __shfl_down_sync(0xffffffffu, part, off);
    if ((tid & 31) == 0) red[tid >> 5] = part;
    __syncthreads();
    if (tid == 0) {
        double tot = 0.0;
        #pragma unroll
        for (int i = 0; i < THREADS / 32; ++i) tot += red[i];
        out[0] = (float)tot;
    }
}

extern "C" void kernel_launch(void* const* d_in, const int* in_sizes, int n_in,
                              void* d_out, int out_size)
{
    const float* theta = (const float*)d_in[0];   // [DEPTH, NQ] float32
    float* out = (float*)d_out;                   // scalar float32
    (void)in_sizes; (void)n_in; (void)out_size;
    lightcone_qsim_kernel<<<1, THREADS>>>(theta, out);
}

// round 13
// speedup vs baseline: 34.5560x; 34.5560x over previous
#include <cuda_runtime.h>
#include <cuda_bf16.h>

// Lightcone-truncated quantum circuit simulation, single-warp register version.
//
// Reference: 25-qubit state vector, 8 layers of (RY on every qubit, CNOT chain
// w=0..23), output = <Z_{qubit 0}> (qubit w <-> bit 24-w; qubit 0 = MSB).
//
// Heisenberg lightcone: conjugating Z_0 backward through the layers, support
// grows by at most one qubit per layer (X on the top support qubit q_m spreads
// to q_{m+1} via CNOT_m; the reverse conjugation order C23..C0 prevents any
// intra-layer cascade; Z terms spread only toward q0). After 8 backward layers
// support is within {q0..q7}; every gate outside conjugates trivially. So
// <Z_0> of the full circuit EXACTLY equals <Z_0> of the circuit truncated to
// the first NQS qubits (RY on q0..NQS-1, CNOT w=0..NQS-2). NQS=9 keeps one
// qubit of safety margin (validated: NQS=12 run matched at rel_err 4.3e-7).
//
// State = 2^9 = 512 fp32 amplitudes, held entirely in one warp's registers:
//   amplitude index i = (lane << 4) | r,  lane in [0,32), r in [0,16)
//   qubit w  <->  bit (8-w):
//     w=0..4 -> lane bits 4..0  (butterflies via __shfl_xor_sync)
//     w=5..8 -> reg  bits 3..0  (in-register, free)
// No shared memory, no __syncthreads, fp32 throughout.

#define NQ     25
#define DEPTH  8
#define NQS    9

__global__ void __launch_bounds__(32, 1)
lightcone_qsim_warp_kernel(const float* __restrict__ theta, float* __restrict__ out)
{
    const int lane = threadIdx.x;
    const unsigned FULL = 0xffffffffu;

    float a[16];
    #pragma unroll
    for (int r = 0; r < 16; ++r) a[r] = 0.0f;
    if (lane == 0) a[0] = 1.0f;   // |0...0>

    #pragma unroll 1
    for (int layer = 0; layer < DEPTH; ++layer) {
        const float* th = theta + layer * NQ;

        // ---- RY gates ----
        // w = 0..4 : lane-bit qubits (bit b = 8-w -> lane bit lb = 4-w)
        #pragma unroll
        for (int w = 0; w < 5; ++w) {
            float s, c;
            sincosf(0.5f * th[w], &s, &c);
            const int lb   = 4 - w;
            const int lmsk = 1 << lb;
            const bool hi  = (lane & lmsk) != 0;
            const float ss = hi ? s : -s;
            #pragma unroll
            for (int r = 0; r < 16; ++r) {
                float p = __shfl_xor_sync(FULL, a[r], lmsk);
                a[r] = fmaf(c, a[r], ss * p);
            }
        }
        // w = 5..8 : register-bit qubits (reg bit rb = 8-w)
        #pragma unroll
        for (int w = 5; w < 9; ++w) {
            float s, c;
            sincosf(0.5f * th[w], &s, &c);
            const int M = 1 << (8 - w);
            #pragma unroll
            for (int r = 0; r < 16; ++r) {
                if ((r & M) == 0) {
                    float a0 = a[r], a1 = a[r | M];
                    a[r]     = fmaf(c, a0, -s * a1);
                    a[r | M] = fmaf(s, a0,  c * a1);
                }
            }
        }

        // ---- CNOT chain w = 0..7 (control qubit w, target qubit w+1) ----
        // w = 0..3 : control lane bit (4-w), target lane bit (3-w)
        #pragma unroll
        for (int w = 0; w < 4; ++w) {
            const int cmsk = 1 << (4 - w);
            const int tmsk = 1 << (3 - w);
            const bool ctrl = (lane & cmsk) != 0;
            #pragma unroll
            for (int r = 0; r < 16; ++r) {
                float p = __shfl_xor_sync(FULL, a[r], tmsk);
                a[r] = ctrl ? p : a[r];
            }
        }
        // w = 4 : control lane bit 0, target reg bit 3
        {
            const bool ctrl = (lane & 1) != 0;
            #pragma unroll
            for (int r = 0; r < 8; ++r) {
                float lo = a[r], hi8 = a[r + 8];
                a[r]     = ctrl ? hi8 : lo;
                a[r + 8] = ctrl ? lo  : hi8;
            }
        }
        // w = 5..7 : control reg bit (8-w), target reg bit (7-w) — free swaps
        #pragma unroll
        for (int w = 5; w < 8; ++w) {
            const int C = 1 << (8 - w);
            const int T = 1 << (7 - w);
            #pragma unroll
            for (int r = 0; r < 16; ++r) {
                if ((r & C) != 0 && (r & T) == 0) {
                    float t = a[r]; a[r] = a[r | T]; a[r | T] = t;
                }
            }
        }
    }

    // ---- <Z_0> : sign from bit 8 = lane bit 4 ----
    float part = 0.0f;
    #pragma unroll
    for (int r = 0; r < 16; ++r) part = fmaf(a[r], a[r], part);
    part = (lane & 16) ? -part : part;

    #pragma unroll
    for (int off = 16; off > 0; off >>= 1)
        part += __shfl_xor_sync(FULL, part, off);

    if (lane == 0) out[0] = part;
}

extern "C" void kernel_launch(void* const* d_in, const int* in_sizes, int n_in,
                              void* d_out, int out_size)
{
    const float* theta = (const float*)d_in[0];   // [DEPTH, NQ] float32
    float* out = (float*)d_out;                   // scalar float32
    (void)in_sizes; (void)n_in; (void)out_size;
    lightcone_qsim_warp_kernel<<<1, 32>>>(theta, out);
}

// round 14
// speedup vs baseline: 74.2315x; 2.1481x over previous
#include <cuda_runtime.h>
#include <cuda_bf16.h>

// Lightcone-truncated quantum circuit sim — single warp, 8 qubits, CNOTs
// absorbed into a GF(2) lane-permutation matrix.
//
// Reference: 25-qubit state, 8 layers of (RY all qubits, CNOT chain w=0..23),
// output <Z_q0> (qubit w <-> bit 24-w). Heisenberg lightcone (tight): support
// of Z_0 conjugated backward through j layers is within {q0..q_{j-1}} — the
// C23..C0 conjugation order prevents intra-layer cascade, so CNOT_7 and all
// gates on q8+ conjugate trivially through all 8 layers. Hence <Z_0> equals
// exactly the 8-qubit truncated circuit (RY q0..q7, CNOT w=0..6).
//
// State: 2^8 = 256 fp32 amps, one warp: amp index = (lane<<3)|reg,
//   q0..q4 -> lane bits 4..0, q5..q7 -> reg bits 2..0.
//
// CNOT absorption: lane-lane CNOT permutes lanes by the LINEAR map
// g(l) = l ^ (l_c ? e_t : 0). The per-layer composite G (w=0..3) satisfies
// G^8 = I. Tracking L = G^k instead of moving data, an RY on logical lane
// bit b needs: shuffle mask m = column b of G^{-k} = G^{8-k}, and sign bit
// parity(lane & row_b(G^k)). The w=4 CNOT control bit is
// parity(lane & row_0(G^{k+1})). All constants, precomputed by hand:
//   G rows: [0x10,0x18,0x1C,0x1E,0x1F]  (out_i = parity(row_i & in))
// After layer 7, L = G^8 = I, so the final Z sign is plain lane bit 4.

#define NQ    25
#define DEPTH 8

__global__ void __launch_bounds__(32, 1)
lightcone_qsim_warp8_kernel(const float* __restrict__ theta, float* __restrict__ out)
{
    const unsigned FULL = 0xffffffffu;
    const int lane = threadIdx.x;

    // ---- parallel sincos precompute: 64 gates, 2 per lane ----
    __shared__ float csb[64], snb[64];
    #pragma unroll
    for (int t = 0; t < 2; ++t) {
        const int idx = lane + 32 * t;                 // idx = layer*8 + w
        const float ang = 0.5f * theta[(idx >> 3) * NQ + (idx & 7)];
        float s, c;
        sincosf(ang, &s, &c);
        csb[idx] = c;
        snb[idx] = s;
    }
    __syncwarp();

    // SHM[k][w]: shfl_xor mask for RY on lane qubit w at layer k  (col_{4-w} of G^{8-k})
    const int SHM[8][5] = {
        {0x10,0x08,0x04,0x02,0x01},   // k=0: I
        {0x18,0x0C,0x06,0x03,0x01},   // k=1: G^7 cols
        {0x14,0x0A,0x05,0x02,0x01},   // k=2: G^6
        {0x1E,0x0F,0x07,0x03,0x01},   // k=3: G^5
        {0x11,0x08,0x04,0x02,0x01},   // k=4: G^4
        {0x19,0x0C,0x06,0x03,0x01},   // k=5: G^3
        {0x15,0x0A,0x05,0x02,0x01},   // k=6: G^2
        {0x1F,0x0F,0x07,0x03,0x01},   // k=7: G^1
    };
    // SGN[k][w]: sign-row for RY on lane qubit w at layer k  (row_{4-w} of G^k)
    const int SGN[8][5] = {
        {0x10,0x08,0x04,0x02,0x01},   // k=0: I
        {0x10,0x18,0x1C,0x1E,0x1F},   // k=1: G
        {0x10,0x08,0x14,0x0A,0x15},   // k=2: G^2
        {0x10,0x18,0x0C,0x06,0x13},   // k=3: G^3
        {0x10,0x08,0x04,0x02,0x11},   // k=4: G^4
        {0x10,0x18,0x1C,0x1E,0x0F},   // k=5: G^5
        {0x10,0x08,0x14,0x0A,0x05},   // k=6: G^6
        {0x10,0x18,0x0C,0x06,0x03},   // k=7: G^7
    };
    // CTR[k]: control row for the lane->reg CNOT (w=4) at layer k  (row_0 of G^{k+1})
    const int CTR[8] = {0x1F,0x15,0x13,0x11,0x0F,0x05,0x03,0x01};

    // ---- state ----
    float a[8];
    #pragma unroll
    for (int r = 0; r < 8; ++r) a[r] = 0.0f;
    if (lane == 0) a[0] = 1.0f;    // |0...0>

    #pragma unroll
    for (int k = 0; k < DEPTH; ++k) {
        // RY on lane qubits q0..q4
        #pragma unroll
        for (int w = 0; w < 5; ++w) {
            const float c = csb[k * 8 + w];
            const float s = snb[k * 8 + w];
            const int   m = SHM[k][w];
            const bool hi = (__popc(lane & SGN[k][w]) & 1) != 0;
            const float ss = hi ? s : -s;
            #pragma unroll
            for (int r = 0; r < 8; ++r) {
                const float p = __shfl_xor_sync(FULL, a[r], m);
                a[r] = fmaf(c, a[r], ss * p);
            }
        }
        // RY on reg qubits q5..q7 (reg bits 2..0)
        #pragma unroll
        for (int w = 5; w < 8; ++w) {
            const float c = csb[k * 8 + w];
            const float s = snb[k * 8 + w];
            const int M = 1 << (7 - w);
            #pragma unroll
            for (int r = 0; r < 8; ++r) {
                if ((r & M) == 0) {
                    const float a0 = a[r], a1 = a[r | M];
                    a[r]     = fmaf(c, a0, -s * a1);
                    a[r | M] = fmaf(s, a0,  c * a1);
                }
            }
        }
        // CNOT w=0..3: absorbed into the permutation matrix (free).
        // CNOT w=4: control = logical lane bit 0 (row_0 of G^{k+1}), target = reg bit 2
        {
            const bool ctrl = (__popc(lane & CTR[k]) & 1) != 0;
            #pragma unroll
            for (int r = 0; r < 4; ++r) {
                const float lo = a[r], hi4 = a[r | 4];
                a[r]     = ctrl ? hi4 : lo;
                a[r | 4] = ctrl ? lo  : hi4;
            }
        }
        // CNOT w=5: control reg bit2, target reg bit1 (register rename)
        { float t = a[4]; a[4] = a[6]; a[6] = t;
          t = a[5]; a[5] = a[7]; a[7] = t; }
        // CNOT w=6: control reg bit1, target reg bit0 (register rename)
        { float t = a[2]; a[2] = a[3]; a[3] = t;
          t = a[6]; a[6] = a[7]; a[7] = t; }
    }

    // ---- <Z_0>: L = G^8 = I, sign = lane bit 4 ----
    float part = 0.0f;
    #pragma unroll
    for (int r = 0; r < 8; ++r) part = fmaf(a[r], a[r], part);
    part = (lane & 16) ? -part : part;

    #pragma unroll
    for (int off = 16; off > 0; off >>= 1)
        part += __shfl_xor_sync(FULL, part, off);

    if (lane == 0) out[0] = part;
}

extern "C" void kernel_launch(void* const* d_in, const int* in_sizes, int n_in,
                              void* d_out, int out_size)
{
    const float* theta = (const float*)d_in[0];   // [DEPTH, NQ] float32
    float* out = (float*)d_out;                   // scalar float32
    (void)in_sizes; (void)n_in; (void)out_size;
    lightcone_qsim_warp8_kernel<<<1, 32>>>(theta, out);
}

// round 15
// speedup vs baseline: 77.0865x; 1.0385x over previous
#include <cuda_runtime.h>
#include <cuda_bf16.h>

// Lightcone-truncated quantum circuit sim — single warp, 8 qubits, GF(2)
// CNOT absorption + layer-0 product state + fused RY pairs.
//
// Reference: 25-qubit state, 8 layers of (RY all qubits, CNOT chain w=0..23),
// output <Z_q0>. Heisenberg lightcone (tight, validated in R13/R14): <Z_0>
// equals exactly the 8-qubit truncated circuit (RY q0..q7, CNOT w=0..6).
//
// State: 256 fp32 amps in one warp: index = (lane<<3)|reg; q0..q4 -> lane
// bits 4..0, q5..q7 -> reg bits 2..0.
//
// Lane-lane CNOTs (w=0..3) are absorbed into the GF(2) matrix L = G^k
// (tables SHM/SGN/CTR validated on hardware in R14, rel_err 1.1e-6).
//
// New this round:
//  * Layer 0 acts on |0>: result is a PRODUCT state, built directly with
//    ~15 multiplies — no shuffles, no butterflies.
//  * Layers 1..7: RY(w0,w1) and RY(w2,w3) each fused into ONE shuffle stage:
//    a' = u0*a + K1*p1 + K2*p2 + K3*p3,  p_i = shfl_xor(a, {m1, m2, m1^m2}),
//    K1 = +-c2*s1 (sign tau1), K2 = +-c1*s2 (sign tau2), K3 = +-s1*s2
//    (sign tau1*tau2 = parity(lane & (g1^g2)); the cross term eta =
//    parity(m2 & g1) is +1 for every layer/pair in these tables).
//    3 serial shuffle stages per layer instead of 5.

#define NQ    25
#define DEPTH 8

__global__ void __launch_bounds__(32, 1)
lightcone_qsim_fused_kernel(const float* __restrict__ theta, float* __restrict__ out)
{
    const unsigned FULL = 0xffffffffu;
    const int lane = threadIdx.x;

    // ---- parallel fast sincos precompute: 64 gates, 2 per lane ----
    __shared__ float csb[64], snb[64];
    #pragma unroll
    for (int t = 0; t < 2; ++t) {
        const int idx = lane + 32 * t;                 // idx = layer*8 + w
        const float ang = 0.5f * theta[(idx >> 3) * NQ + (idx & 7)];
        float s, c;
        __sincosf(ang, &s, &c);
        csb[idx] = c;
        snb[idx] = s;
    }
    __syncwarp();

    // SHM[k][w]: shfl_xor mask for RY on lane qubit w at layer k (col of G^{8-k})
    const int SHM[8][5] = {
        {0x10,0x08,0x04,0x02,0x01},
        {0x18,0x0C,0x06,0x03,0x01},
        {0x14,0x0A,0x05,0x02,0x01},
        {0x1E,0x0F,0x07,0x03,0x01},
        {0x11,0x08,0x04,0x02,0x01},
        {0x19,0x0C,0x06,0x03,0x01},
        {0x15,0x0A,0x05,0x02,0x01},
        {0x1F,0x0F,0x07,0x03,0x01},
    };
    // SGN[k][w]: sign row (row of G^k)
    const int SGN[8][5] = {
        {0x10,0x08,0x04,0x02,0x01},
        {0x10,0x18,0x1C,0x1E,0x1F},
        {0x10,0x08,0x14,0x0A,0x15},
        {0x10,0x18,0x0C,0x06,0x13},
        {0x10,0x08,0x04,0x02,0x11},
        {0x10,0x18,0x1C,0x1E,0x0F},
        {0x10,0x08,0x14,0x0A,0x05},
        {0x10,0x18,0x0C,0x06,0x03},
    };
    // CTR[k]: control row for the lane->reg CNOT (w=4) at layer k (row_0 of G^{k+1})
    const int CTR[8] = {0x1F,0x15,0x13,0x11,0x0F,0x05,0x03,0x01};

    float a[8];

    // ---- layer 0: product state (|0> -> prod of RY factors), then CNOT tail ----
    {
        float P = 1.0f;
        #pragma unroll
        for (int w = 0; w < 5; ++w)
            P *= ((lane >> (4 - w)) & 1) ? snb[w] : csb[w];
        #pragma unroll
        for (int r = 0; r < 8; ++r) {
            const float q = ((r & 4) ? snb[5] : csb[5])
                          * ((r & 2) ? snb[6] : csb[6])
                          * ((r & 1) ? snb[7] : csb[7]);
            a[r] = P * q;
        }
        // CNOT w=4 (ctrl = logical lane bit 0 after absorption)
        const bool ctrl = (__popc(lane & CTR[0]) & 1) != 0;
        #pragma unroll
        for (int r = 0; r < 4; ++r) {
            const float lo = a[r], hi4 = a[r | 4];
            a[r]     = ctrl ? hi4 : lo;
            a[r | 4] = ctrl ? lo  : hi4;
        }
        // CNOT w=5, w=6 (register renames)
        { float t = a[4]; a[4] = a[6]; a[6] = t;
          t = a[5]; a[5] = a[7]; a[7] = t; }
        { float t = a[2]; a[2] = a[3]; a[3] = t;
          t = a[6]; a[6] = a[7]; a[7] = t; }
    }

    // ---- layers 1..7 ----
    #pragma unroll
    for (int k = 1; k < DEPTH; ++k) {
        const float* tc = &csb[k * 8];
        const float* ts = &snb[k * 8];

        // fused RY pairs (w0,w1) and (w2,w3): one shuffle stage each
        #pragma unroll
        for (int pr = 0; pr < 2; ++pr) {
            const int wA = 2 * pr, wB = 2 * pr + 1;
            const float c1 = tc[wA], s1 = ts[wA];
            const float c2 = tc[wB], s2 = ts[wB];
            const int m1 = SHM[k][wA], m2 = SHM[k][wB], m3 = m1 ^ m2;
            const int g1 = SGN[k][wA], g2 = SGN[k][wB];
            const float u0 = c1 * c2, uA = c2 * s1, uB = c1 * s2, uC = s1 * s2;
            const bool b1  = (__popc(lane & g1) & 1) != 0;
            const bool b2  = (__popc(lane & g2) & 1) != 0;
            const bool b12 = b1 ^ b2;
            const float K1 = b1  ?  uA : -uA;
            const float K2 = b2  ?  uB : -uB;
            const float K3 = b12 ? -uC :  uC;   // tau1*tau2; eta = +1 (verified)
            #pragma unroll
            for (int r = 0; r < 8; ++r) {
                const float p1 = __shfl_xor_sync(FULL, a[r], m1);
                const float p2 = __shfl_xor_sync(FULL, a[r], m2);
                const float p3 = __shfl_xor_sync(FULL, a[r], m3);
                a[r] = fmaf(u0, a[r], fmaf(K1, p1, fmaf(K2, p2, K3 * p3)));
            }
        }
        // single RY w4
        {
            const float c = tc[4], s = ts[4];
            const int m = SHM[k][4];
            const bool hi = (__popc(lane & SGN[k][4]) & 1) != 0;
            const float ss = hi ? s : -s;
            #pragma unroll
            for (int r = 0; r < 8; ++r) {
                const float ca = c * a[r];                    // off critical path
                const float p = __shfl_xor_sync(FULL, a[r], m);
                a[r] = fmaf(ss, p, ca);
            }
        }
        // reg RYs q5..q7 (reg bits 2..0)
        #pragma unroll
        for (int w = 5; w < 8; ++w) {
            const float c = tc[w], s = ts[w];
            const int M = 1 << (7 - w);
            #pragma unroll
            for (int r = 0; r < 8; ++r) {
                if ((r & M) == 0) {
                    const float a0 = a[r], a1 = a[r | M];
                    a[r]     = fmaf(c, a0, -s * a1);
                    a[r | M] = fmaf(s, a0,  c * a1);
                }
            }
        }
        // CNOT tail: w=4 select, w=5/w=6 renames
        {
            const bool ctrl = (__popc(lane & CTR[k]) & 1) != 0;
            #pragma unroll
            for (int r = 0; r < 4; ++r) {
                const float lo = a[r], hi4 = a[r | 4];
                a[r]     = ctrl ? hi4 : lo;
                a[r | 4] = ctrl ? lo  : hi4;
            }
            { float t = a[4]; a[4] = a[6]; a[6] = t;
              t = a[5]; a[5] = a[7]; a[7] = t; }
            { float t = a[2]; a[2] = a[3]; a[3] = t;
              t = a[6]; a[6] = a[7]; a[7] = t; }
        }
    }

    // ---- <Z_0>: L = G^8 = I, sign = lane bit 4 ----
    float part = 0.0f;
    #pragma unroll
    for (int r = 0; r < 8; ++r) part = fmaf(a[r], a[r], part);
    part = (lane & 16) ? -part : part;

    #pragma unroll
    for (int off = 16; off > 0; off >>= 1)
        part += __shfl_xor_sync(FULL, part, off);

    if (lane == 0) out[0] = part;
}

extern "C" void kernel_launch(void* const* d_in, const int* in_sizes, int n_in,
                              void* d_out, int out_size)
{
    const float* theta = (const float*)d_in[0];   // [DEPTH, NQ] float32
    float* out = (float*)d_out;                   // scalar float32
    (void)in_sizes; (void)n_in; (void)out_size;
    lightcone_qsim_fused_kernel<<<1, 32>>>(theta, out);
}